// round 3
// baseline (speedup 1.0000x reference)
#include <cuda_runtime.h>
#include <cuda_bf16.h>
#include <cstdint>

typedef __nv_bfloat16 bf16;

#define H_ 1024
#define V_ 32000
#define B_ 16
#define T_ 256
#define R_ 4096   // B_*T_
#define NB 128    // persistent recurrence blocks

// ---------------- static device scratch (allocations are forbidden) ----------------
__device__ bf16  g_Xhi[R_ * H_];
__device__ bf16  g_Xlo[R_ * H_];
__device__ bf16  g_WcatT_hi[4 * H_ * H_];   // [n4][k]
__device__ bf16  g_WcatT_lo[4 * H_ * H_];
__device__ float g_bcat[4 * H_];
__device__ float g_XG[(size_t)R_ * 4 * H_]; // precomputed x-gate contributions (+bias)
__device__ float g_Upack[NB * H_ * 32];     // U repacked for recurrence
__device__ float g_Hbuf[H_ * 16];           // h, layout [n][b]
__device__ bf16  g_HShi[R_ * H_];
__device__ bf16  g_HSlo[R_ * H_];
__device__ bf16  g_WoutT_hi[32768000];      // V_*H_, layout [n][k]
__device__ bf16  g_WoutT_lo[32768000];
__device__ unsigned g_ctr[256];             // per-step grid-barrier counters

// ---------------- prep kernels ----------------
__global__ void zero_ctr_kernel() {
    if (threadIdx.x < 256) g_ctr[threadIdx.x] = 0u;
}

__global__ void bcat_kernel(const float* __restrict__ bf_, const float* __restrict__ bi_,
                            const float* __restrict__ bc_, const float* __restrict__ bo_) {
    int i = blockIdx.x * blockDim.x + threadIdx.x;
    if (i < 4 * H_) {
        int g = i >> 10, n = i & (H_ - 1);
        const float* b = (g == 0) ? bf_ : (g == 1) ? bi_ : (g == 2) ? bc_ : bo_;
        g_bcat[i] = b[n];
    }
}

__global__ void gather_split_kernel(const int* __restrict__ tokens,
                                    const float* __restrict__ emb) {
    for (int idx = blockIdx.x * blockDim.x + threadIdx.x; idx < R_ * H_;
         idx += gridDim.x * blockDim.x) {
        int r = idx >> 10, k = idx & (H_ - 1);
        float v = emb[(size_t)tokens[r] * H_ + k];
        bf16 h = __float2bfloat16(v);
        g_Xhi[idx] = h;
        g_Xlo[idx] = __float2bfloat16(v - __bfloat162float(h));
    }
}

// WcatT[n4][k] = w_g[k][n]  (n4 = g*1024 + n)
__global__ void wcatT_split_kernel(const float* __restrict__ wf, const float* __restrict__ wi,
                                   const float* __restrict__ wc, const float* __restrict__ wo) {
    for (int idx = blockIdx.x * blockDim.x + threadIdx.x; idx < 4 * H_ * H_;
         idx += gridDim.x * blockDim.x) {
        int k = idx & 1023;
        int n4 = idx >> 10;
        int g = n4 >> 10, n = n4 & 1023;
        const float* w = (g == 0) ? wf : (g == 1) ? wi : (g == 2) ? wc : wo;
        float v = w[(size_t)k * H_ + n];
        bf16 h = __float2bfloat16(v);
        g_WcatT_hi[idx] = h;
        g_WcatT_lo[idx] = __float2bfloat16(v - __bfloat162float(h));
    }
}

// WoutT[n][k] = w_out[k][n]
__global__ void woutT_split_kernel(const float* __restrict__ wout) {
    for (long long idx = (long long)blockIdx.x * blockDim.x + threadIdx.x;
         idx < (long long)V_ * H_; idx += (long long)gridDim.x * blockDim.x) {
        int k = (int)(idx & 1023);
        int n = (int)(idx >> 10);
        float v = wout[(size_t)k * V_ + n];
        bf16 h = __float2bfloat16(v);
        g_WoutT_hi[idx] = h;
        g_WoutT_lo[idx] = __float2bfloat16(v - __bfloat162float(h));
    }
}

// Upack[(i*1024 + k)*32 + l] = u_g[k][8*i + j], where g = l>>3, j = l&7
__global__ void pack_u_kernel(const float* __restrict__ uf, const float* __restrict__ ui,
                              const float* __restrict__ uc, const float* __restrict__ uo) {
    for (int idx = blockIdx.x * blockDim.x + threadIdx.x; idx < NB * H_ * 32;
         idx += gridDim.x * blockDim.x) {
        int l = idx & 31;
        int k = (idx >> 5) & 1023;
        int i = idx >> 15;
        int g = l >> 3, j = l & 7;
        const float* u = (g == 0) ? uf : (g == 1) ? ui : (g == 2) ? uc : uo;
        g_Upack[idx] = u[(size_t)k * H_ + 8 * i + j];
    }
}

// ---------------- split-bf16 GEMM: C[M,N] = A[M,K] * B^T[N,K] + bias ----------------
// A [M][K] row-major (hi/lo), Bt [N][K] row-major (hi/lo). Tiles 128x128, BK=32.
// C = Ah*Bh + Ah*Bl + Al*Bh (fp32 accum), rel err ~1e-5.

__device__ __forceinline__ void mma16816(float c[4], const uint32_t a[4], uint32_t b0,
                                         uint32_t b1) {
    asm volatile(
        "mma.sync.aligned.m16n8k16.row.col.f32.bf16.bf16.f32 "
        "{%0,%1,%2,%3}, {%4,%5,%6,%7}, {%8,%9}, {%0,%1,%2,%3};\n"
        : "+f"(c[0]), "+f"(c[1]), "+f"(c[2]), "+f"(c[3])
        : "r"(a[0]), "r"(a[1]), "r"(a[2]), "r"(a[3]), "r"(b0), "r"(b1));
}

struct Stage {
    uint4 ra[2][2];
    uint4 rb[2][2];
};

__device__ __forceinline__ void g_load(Stage& s, const bf16* __restrict__ Ahi,
                                       const bf16* __restrict__ Alo,
                                       const bf16* __restrict__ Bhi,
                                       const bf16* __restrict__ Blo, int bm0, int bn0, int K,
                                       int k0, int tid) {
#pragma unroll
    for (int q = 0; q < 2; q++) {
        int idx = q * 256 + tid;
        int r = idx >> 2, cg = idx & 3;
        s.ra[0][q] = *(const uint4*)(Ahi + (size_t)(bm0 + r) * K + k0 + cg * 8);
        s.ra[1][q] = *(const uint4*)(Alo + (size_t)(bm0 + r) * K + k0 + cg * 8);
        s.rb[0][q] = *(const uint4*)(Bhi + (size_t)(bn0 + r) * K + k0 + cg * 8);
        s.rb[1][q] = *(const uint4*)(Blo + (size_t)(bn0 + r) * K + k0 + cg * 8);
    }
}

__device__ __forceinline__ void g_store(const Stage& s, bf16 (*As)[128][40], bf16 (*Bs)[128][40],
                                        int tid) {
#pragma unroll
    for (int q = 0; q < 2; q++) {
        int idx = q * 256 + tid;
        int r = idx >> 2, cg = idx & 3;
        *(uint4*)&As[0][r][cg * 8] = s.ra[0][q];
        *(uint4*)&As[1][r][cg * 8] = s.ra[1][q];
        *(uint4*)&Bs[0][r][cg * 8] = s.rb[0][q];
        *(uint4*)&Bs[1][r][cg * 8] = s.rb[1][q];
    }
}

__global__ __launch_bounds__(256) void gemm_split_kernel(
    const bf16* __restrict__ Ahi, const bf16* __restrict__ Alo, const bf16* __restrict__ Bhi,
    const bf16* __restrict__ Blo, const float* __restrict__ bias, float* __restrict__ C, int M,
    int N, int K) {
    __shared__ bf16 As[2][128][40];
    __shared__ bf16 Bs[2][128][40];

    const int tid = threadIdx.x;
    const int bn0 = blockIdx.x * 128;
    const int bm0 = blockIdx.y * 128;
    const int lane = tid & 31, warp = tid >> 5;
    const int wm = warp & 3, wn = warp >> 2;
    const int g = lane >> 2, tg = lane & 3;

    float acc[2][8][4];
#pragma unroll
    for (int mi = 0; mi < 2; mi++)
#pragma unroll
        for (int nj = 0; nj < 8; nj++)
#pragma unroll
            for (int e = 0; e < 4; e++) acc[mi][nj][e] = 0.f;

    Stage st;
    g_load(st, Ahi, Alo, Bhi, Blo, bm0, bn0, K, 0, tid);
    g_store(st, As, Bs, tid);
    __syncthreads();

    const int nk = K / 32;
    for (int kt = 0; kt < nk; kt++) {
        if (kt + 1 < nk) g_load(st, Ahi, Alo, Bhi, Blo, bm0, bn0, K, (kt + 1) * 32, tid);
#pragma unroll
        for (int ks = 0; ks < 32; ks += 16) {
            uint32_t ah[2][4], al[2][4];
#pragma unroll
            for (int mi = 0; mi < 2; mi++) {
                int r0 = wm * 32 + mi * 16 + g;
                ah[mi][0] = *(const uint32_t*)&As[0][r0][ks + 2 * tg];
                ah[mi][1] = *(const uint32_t*)&As[0][r0 + 8][ks + 2 * tg];
                ah[mi][2] = *(const uint32_t*)&As[0][r0][ks + 2 * tg + 8];
                ah[mi][3] = *(const uint32_t*)&As[0][r0 + 8][ks + 2 * tg + 8];
                al[mi][0] = *(const uint32_t*)&As[1][r0][ks + 2 * tg];
                al[mi][1] = *(const uint32_t*)&As[1][r0 + 8][ks + 2 * tg];
                al[mi][2] = *(const uint32_t*)&As[1][r0][ks + 2 * tg + 8];
                al[mi][3] = *(const uint32_t*)&As[1][r0 + 8][ks + 2 * tg + 8];
            }
#pragma unroll
            for (int nj = 0; nj < 8; nj++) {
                int n = wn * 64 + nj * 8 + g;
                uint32_t bh0 = *(const uint32_t*)&Bs[0][n][ks + 2 * tg];
                uint32_t bh1 = *(const uint32_t*)&Bs[0][n][ks + 2 * tg + 8];
                uint32_t bl0 = *(const uint32_t*)&Bs[1][n][ks + 2 * tg];
                uint32_t bl1 = *(const uint32_t*)&Bs[1][n][ks + 2 * tg + 8];
#pragma unroll
                for (int mi = 0; mi < 2; mi++) {
                    mma16816(acc[mi][nj], ah[mi], bh0, bh1);
                    mma16816(acc[mi][nj], ah[mi], bl0, bl1);
                    mma16816(acc[mi][nj], al[mi], bh0, bh1);
                }
            }
        }
        __syncthreads();
        if (kt + 1 < nk) {
            g_store(st, As, Bs, tid);
            __syncthreads();
        }
    }

#pragma unroll
    for (int mi = 0; mi < 2; mi++) {
#pragma unroll
        for (int nj = 0; nj < 8; nj++) {
            int r = bm0 + wm * 32 + mi * 16 + g;
            int nc = bn0 + wn * 64 + nj * 8 + 2 * tg;
            float b0 = bias[nc], b1 = bias[nc + 1];
            float2 v0 = make_float2(acc[mi][nj][0] + b0, acc[mi][nj][1] + b1);
            float2 v1 = make_float2(acc[mi][nj][2] + b0, acc[mi][nj][3] + b1);
            *(float2*)&C[(size_t)r * N + nc] = v0;
            *(float2*)&C[(size_t)(r + 8) * N + nc] = v1;
        }
    }
}

// ---------------- persistent LSTM recurrence ----------------
// 128 blocks x 256 threads, block i owns h-cols [8i, 8i+8).
// Thread (l = tid&31 -> (gate g=l>>3, col j=l&7), rg = (tid>>5)&3 -> rows 4rg..4rg+3,
// kh = tid>>7 -> k half). One grid barrier per step via g_ctr.

extern __shared__ float recur_smem[];

__global__ __launch_bounds__(256) void recur_kernel() {
    float* hsm = recur_smem;        // 16384 floats, layout [k][16]
    float* Gs = hsm + 16384;        // 512:  [g][r][j] = g*128 + r*8 + j
    float* red = Gs + 512;          // 512:  kh=1 partials
    float* csm = red + 512;         // 128:  cell state (block-owned cols)

    const int i = blockIdx.x;
    const int tid = threadIdx.x;
    const int l = tid & 31;
    const int rg = (tid >> 5) & 3;
    const int kh = tid >> 7;
    const int gg = l >> 3, jj = l & 7;

    if (tid < 128) csm[tid] = 0.f;
    const float* up_base = g_Upack + ((size_t)i * 1024 + kh * 512) * 32 + l;

    for (int t = 0; t < 256; t++) {
        float a0 = 0.f, a1 = 0.f, a2 = 0.f, a3 = 0.f;
        if (t > 0) {
            const float4* src = (const float4*)g_Hbuf;
            float4* dst = (float4*)hsm;
#pragma unroll
            for (int q = 0; q < 16; q++) dst[tid + q * 256] = src[tid + q * 256];
            __syncthreads();
            const float* up = up_base;
            const float4* hp = (const float4*)(hsm + kh * 512 * 16 + rg * 4);
#pragma unroll 8
            for (int k = 0; k < 512; k++) {
                float u = up[k * 32];
                float4 hv = hp[k * 4];
                a0 += hv.x * u;
                a1 += hv.y * u;
                a2 += hv.z * u;
                a3 += hv.w * u;
            }
        }
        // combine k-halves
        if (kh == 1) {
            red[(tid - 128) * 4 + 0] = a0;
            red[(tid - 128) * 4 + 1] = a1;
            red[(tid - 128) * 4 + 2] = a2;
            red[(tid - 128) * 4 + 3] = a3;
        }
        __syncthreads();
        if (kh == 0) {
            a0 += red[tid * 4 + 0];
            a1 += red[tid * 4 + 1];
            a2 += red[tid * 4 + 2];
            a3 += red[tid * 4 + 3];
            float* gp = Gs + gg * 128 + jj;
            gp[(4 * rg + 0) * 8] = a0;
            gp[(4 * rg + 1) * 8] = a1;
            gp[(4 * rg + 2) * 8] = a2;
            gp[(4 * rg + 3) * 8] = a3;
        }
        __syncthreads();
        if (tid < 128) {
            int r = tid >> 3, j = tid & 7;
            int n = 8 * i + j;
            int row = r * 256 + t;
            const float* xg = g_XG + (size_t)row * 4096 + n;
            float pf = Gs[0 * 128 + r * 8 + j] + xg[0];
            float pi = Gs[1 * 128 + r * 8 + j] + xg[1024];
            float pc = Gs[2 * 128 + r * 8 + j] + xg[2048];
            float po = Gs[3 * 128 + r * 8 + j] + xg[3072];
            float f = 1.f / (1.f + expf(-pf));
            float ig = 1.f / (1.f + expf(-pi));
            float cd = tanhf(pc);
            float o = 1.f / (1.f + expf(-po));
            float c = f * csm[tid] + ig * cd;
            csm[tid] = c;
            float h = o * tanhf(c);
            g_Hbuf[n * 16 + r] = h;
            size_t hidx = (size_t)row * 1024 + n;
            bf16 hh = __float2bfloat16(h);
            g_HShi[hidx] = hh;
            g_HSlo[hidx] = __float2bfloat16(h - __bfloat162float(hh));
        }
        if (t < 255) {
            __threadfence();
            __syncthreads();
            if (tid == 0) {
                atomicAdd(&g_ctr[t], 1u);
                while (*((volatile unsigned*)&g_ctr[t]) < (unsigned)NB) {
                }
                __threadfence();
            }
            __syncthreads();
        }
    }
}

// ---------------- launch ----------------
extern "C" void kernel_launch(void* const* d_in, const int* in_sizes, int n_in, void* d_out,
                              int out_size) {
    const int* tokens = (const int*)d_in[0];
    const float* emb = (const float*)d_in[1];
    const float* w_f = (const float*)d_in[2];
    const float* u_f = (const float*)d_in[3];
    const float* b_f = (const float*)d_in[4];
    const float* w_i = (const float*)d_in[5];
    const float* u_i = (const float*)d_in[6];
    const float* b_i = (const float*)d_in[7];
    const float* w_c = (const float*)d_in[8];
    const float* u_c = (const float*)d_in[9];
    const float* b_c = (const float*)d_in[10];
    const float* w_o = (const float*)d_in[11];
    const float* u_o = (const float*)d_in[12];
    const float* b_o = (const float*)d_in[13];
    const float* w_out = (const float*)d_in[14];
    const float* b_out = (const float*)d_in[15];
    float* out = (float*)d_out;

    const int recur_smem_bytes = (16384 + 512 + 512 + 128) * 4;  // 70144
    cudaFuncSetAttribute(recur_kernel, cudaFuncAttributeMaxDynamicSharedMemorySize,
                         recur_smem_bytes);

    void *p_xhi, *p_xlo, *p_wch, *p_wcl, *p_bcat, *p_xg, *p_hshi, *p_hslo, *p_woh, *p_wol;
    cudaGetSymbolAddress(&p_xhi, g_Xhi);
    cudaGetSymbolAddress(&p_xlo, g_Xlo);
    cudaGetSymbolAddress(&p_wch, g_WcatT_hi);
    cudaGetSymbolAddress(&p_wcl, g_WcatT_lo);
    cudaGetSymbolAddress(&p_bcat, g_bcat);
    cudaGetSymbolAddress(&p_xg, g_XG);
    cudaGetSymbolAddress(&p_hshi, g_HShi);
    cudaGetSymbolAddress(&p_hslo, g_HSlo);
    cudaGetSymbolAddress(&p_woh, g_WoutT_hi);
    cudaGetSymbolAddress(&p_wol, g_WoutT_lo);

    zero_ctr_kernel<<<1, 256>>>();
    bcat_kernel<<<16, 256>>>(b_f, b_i, b_c, b_o);
    gather_split_kernel<<<4096, 256>>>(tokens, emb);
    wcatT_split_kernel<<<4096, 256>>>(w_f, w_i, w_c, w_o);
    pack_u_kernel<<<4096, 256>>>(u_f, u_i, u_c, u_o);
    woutT_split_kernel<<<8192, 256>>>(w_out);

    // XG = X @ Wcat + bcat   (M=4096, N=4096, K=1024)
    gemm_split_kernel<<<dim3(4096 / 128, 4096 / 128), 256>>>(
        (const bf16*)p_xhi, (const bf16*)p_xlo, (const bf16*)p_wch, (const bf16*)p_wcl,
        (const float*)p_bcat, (float*)p_xg, R_, 4 * H_, H_);

    // sequential LSTM recurrence (persistent, 1 grid barrier per step)
    recur_kernel<<<NB, 256, recur_smem_bytes>>>();

    // logits = HS @ w_out + b_out   (M=4096, N=32000, K=1024)
    gemm_split_kernel<<<dim3(V_ / 128, R_ / 128), 256>>>(
        (const bf16*)p_hshi, (const bf16*)p_hslo, (const bf16*)p_woh, (const bf16*)p_wol, b_out,
        out, R_, V_, H_);
}